// round 4
// baseline (speedup 1.0000x reference)
#include <cuda_runtime.h>
#include <cuda_bf16.h>
#include <cstdint>

// ProposalTarget: B=16, A=9, H=W=128, S=2048 (fixed).
// R3 finding: TMA store good, but 39KB CTAs -> 2-3 resident CTAs/SM and the
// bar+TMA-wait tail exposed. R4: half-size CTAs (TPB=128, 18KB staging) ->
// ~9 resident CTAs/SM; tails hidden across CTAs.

#define B_   16
#define A_   9
#define H_   128
#define W_   128
#define HW_  (H_ * W_)            // 16384
#define AHW_ (A_ * HW_)           // 147456
#define NTOT (B_ * AHW_)          // 2359296
#define TPB  128
#define VEC  4
#define ELEMS_PER_BLK (TPB * VEC)         // 512
#define OUT_F_PER_BLK (ELEMS_PER_BLK * 9) // 4608 floats
#define OUT_V_PER_BLK (OUT_F_PER_BLK / 4) // 1152 float4
#define OUT_BYTES_PER_BLK (OUT_F_PER_BLK * 4)  // 18432
#define BLKS_PER_BA (HW_ / ELEMS_PER_BLK)      // 32 blocks per (b,a)

__device__ __forceinline__ uint32_t smem_u32(const void* p) {
    return (uint32_t)__cvta_generic_to_shared(p);
}

__global__ __launch_bounds__(TPB)
void proposal_target_kernel(const float* __restrict__ cla_map,
                            const float* __restrict__ reg_map,
                            const float* __restrict__ anchor,
                            float* __restrict__ out)
{
    __shared__ float4 s_anc[W_];                           // 2 KB anchors
    __shared__ __align__(128) float4 s_out[OUT_V_PER_BLK]; // 18 KB staged output

    const int tid = threadIdx.x;

    // Block-uniform (b, a): 32 blocks per (b,a) pair
    const int ba    = blockIdx.x / BLKS_PER_BA;   // 0..143
    const int a_blk = ba % A_;
    const int b_blk = ba / A_;

    // Preload anchors for this a: row = w * 129 * a, cols 2..5
    {
        const int row = tid * 129 * a_blk;        // tid == w (TPB == W_)
        const float* p = anchor + (size_t)row * 6 + 2;
        s_anc[tid] = make_float4(__ldg(p + 0), __ldg(p + 1), __ldg(p + 2), __ldg(p + 3));
    }
    __syncthreads();

    const int i0 = blockIdx.x * ELEMS_PER_BLK + tid * VEC;
    const int hw = i0 & (HW_ - 1);
    const int w0 = i0 & (W_ - 1);

    // 128-bit coalesced input loads
    const size_t cla_base = ((size_t)(b_blk * (2 * A_) + 2 * a_blk)) * HW_ + hw;
    const float4 c0v = *reinterpret_cast<const float4*>(cla_map + cla_base);
    const float4 c1v = *reinterpret_cast<const float4*>(cla_map + cla_base + HW_);

    const size_t reg_base = ((size_t)(b_blk * (4 * A_) + 4 * a_blk)) * HW_ + hw;
    const float4 txv = *reinterpret_cast<const float4*>(reg_map + reg_base);
    const float4 tyv = *reinterpret_cast<const float4*>(reg_map + reg_base + HW_);
    const float4 twv = *reinterpret_cast<const float4*>(reg_map + reg_base + 2 * HW_);
    const float4 thv = *reinterpret_cast<const float4*>(reg_map + reg_base + 3 * HW_);

    const float S    = 2048.0f;
    const float invS = 1.0f / 2048.0f;

    float vout[VEC * 9];

    const float* c0a = &c0v.x; const float* c1a = &c1v.x;
    const float* txa = &txv.x; const float* tya = &tyv.x;
    const float* twa = &twv.x; const float* tha = &thv.x;

    #pragma unroll
    for (int e = 0; e < VEC; e++) {
        const float4 anc = s_anc[w0 + e];
        const float acx = anc.x, acy = anc.y, aw = anc.z, ah = anc.w;

        const float fg = 1.0f / (1.0f + expf(c0a[e] - c1a[e]));  // sigmoid(c1-c0)

        const float cx = (txa[e] * aw + acx) * S;
        const float cy = (tya[e] * ah + acy) * S;
        const float wd = expf(twa[e]) * aw * S;
        const float hd = expf(tha[e]) * ah * S;

        const float ltx = cx - 0.5f * wd;
        const float lty = cy - 0.5f * hd;
        const float rbx = cx + 0.5f * wd;
        const float rby = cy + 0.5f * hd;

        const bool valid = (fg > 0.7f) & (ltx >= 0.0f) & (lty >= 0.0f)
                         & (rbx <= S)  & (rby <= S);
        const float m  = valid ? 1.0f : 0.0f;
        const float mS = m * invS;

        vout[e * 9 + 0] = ltx * m;
        vout[e * 9 + 1] = lty * m;
        vout[e * 9 + 2] = rbx * m;
        vout[e * 9 + 3] = rby * m;
        vout[e * 9 + 4] = cx * mS;
        vout[e * 9 + 5] = cy * mS;
        vout[e * 9 + 6] = wd * mS;
        vout[e * 9 + 7] = hd * mS;
        vout[e * 9 + 8] = m;
    }

    // Stage: 9 x STS.128 (byte offset tid*144, 16B aligned, conflict-free)
    {
        float4* sp = s_out + tid * 9;
        const float4* vp = reinterpret_cast<const float4*>(vout);
        #pragma unroll
        for (int j = 0; j < 9; j++) sp[j] = vp[j];
    }
    __syncthreads();

    // TMA bulk store: 18 KB contiguous smem -> gmem, one thread issues.
    if (tid == 0) {
        asm volatile("fence.proxy.async.shared::cta;" ::: "memory");
        float* gdst = out + (size_t)blockIdx.x * OUT_F_PER_BLK;
        asm volatile(
            "cp.async.bulk.global.shared::cta.bulk_group [%0], [%1], %2;"
            :: "l"(gdst), "r"(smem_u32(s_out)), "n"(OUT_BYTES_PER_BLK)
            : "memory");
        asm volatile("cp.async.bulk.commit_group;" ::: "memory");
        asm volatile("cp.async.bulk.wait_group 0;" ::: "memory");
    }
}

extern "C" void kernel_launch(void* const* d_in, const int* in_sizes, int n_in,
                              void* d_out, int out_size)
{
    const float* cla_map = (const float*)d_in[0];
    const float* reg_map = (const float*)d_in[1];
    const float* anchor  = (const float*)d_in[2];
    float*       out     = (float*)d_out;

    const int grid = NTOT / ELEMS_PER_BLK;   // 4608
    proposal_target_kernel<<<grid, TPB>>>(cla_map, reg_map, anchor, out);
}